// round 8
// baseline (speedup 1.0000x reference)
#include <cuda_runtime.h>
#include <cuda_bf16.h>
#include <cmath>
#include <complex>
#include <cstring>
#include <cstdint>

// ---------------- Host Wigner-3j (mirror of reference) ----------------
typedef std::complex<double> cd;
static double s_fact(int n){double r=1.0;for(int i=2;i<=n;++i)r*=i;return r;}
static double su2_cg(int j1,int m1,int j2,int m2,int j3,int m3){
    if(m3!=m1+m2)return 0.0;
    int vmin=-j1+j2+m3; if(-j1+m1>vmin)vmin=-j1+m1; if(0>vmin)vmin=0;
    int vmax=j2+j3+m1; if(j3-j1+j2<vmax)vmax=j3-j1+j2; if(j3+m3<vmax)vmax=j3+m3;
    double pref=std::sqrt((2.0*j3+1.0)*s_fact(j3+j1-j2)*s_fact(j3-j1+j2)*s_fact(j1+j2-j3)/s_fact(j1+j2+j3+1)
        *s_fact(j3+m3)*s_fact(j3-m3)/(s_fact(j1-m1)*s_fact(j1+m1)*s_fact(j2-m2)*s_fact(j2+m2)));
    double s=0.0;
    for(int v=vmin;v<=vmax;++v){
        double sg=((v+j2+m2)&1)?-1.0:1.0;
        s+=sg/s_fact(v)*s_fact(j2+j3+m1-v)*s_fact(j1-m1+v)
          /(s_fact(j3-j1+j2-v)*s_fact(j3+m3-v)*s_fact(v+j1-j2-m3));
    }
    return pref*s;
}
static void qmat(int l,cd*Q){
    int n=2*l+1; for(int i=0;i<n*n;++i)Q[i]=cd(0,0);
    double is2=1.0/std::sqrt(2.0);
    for(int m=-l;m<0;++m){Q[(l+m)*n+(l-m)]=cd(is2,0);Q[(l+m)*n+(l+m)]=cd(0,-is2);}
    Q[l*n+l]=cd(1,0);
    for(int m=1;m<=l;++m){double sg=(m&1)?-1.0:1.0;Q[(l+m)*n+(l+m)]=cd(sg*is2,0);Q[(l+m)*n+(l-m)]=cd(0,sg*is2);}
    cd f(1,0),mi(0,-1); for(int t=0;t<l;++t)f*=mi;
    for(int i=0;i<n*n;++i)Q[i]*=f;
}
static void wigner3j_scaled(int l1,int l2,int l3,float alpha,float*out){
    int n1=2*l1+1,n2=2*l2+1,n3=2*l3+1;
    cd Csu2[125];
    for(int i=0;i<n1;++i)for(int k=0;k<n2;++k)for(int n=0;n<n3;++n)
        Csu2[(i*n2+k)*n3+n]=cd(su2_cg(l1,i-l1,l2,k-l2,l3,n-l3),0);
    cd Q1[25],Q2[25],Q3[25]; qmat(l1,Q1);qmat(l2,Q2);qmat(l3,Q3);
    double Cr[125],norm2=0.0;
    for(int j=0;j<n1;++j)for(int l=0;l<n2;++l)for(int m=0;m<n3;++m){
        cd acc(0,0);
        for(int i=0;i<n1;++i)for(int k=0;k<n2;++k)for(int n=0;n<n3;++n)
            acc+=Q1[i*n1+j]*Q2[k*n2+l]*std::conj(Q3[n*n3+m])*Csu2[(i*n2+k)*n3+n];
        Cr[(j*n2+l)*n3+m]=acc.real(); norm2+=acc.real()*acc.real();
    }
    double inv=(double)alpha/std::sqrt(norm2);
    for(int t=0;t<n1*n2*n3;++t)out[t]=(float)(Cr[t]*inv);
}
struct TPCoef{float c220[25];float c121[45];float c112[45];};

// ---------------- Scratch (static device globals) ----------------
#define NMAX 50048
__device__ float g_xl[(size_t)NMAX*8*128];
__device__ float g_xr[(size_t)NMAX*8*128];
__device__ __nv_bfloat16 g_tph[(size_t)NMAX*9*128];
__device__ __nv_bfloat16 g_tpl[(size_t)NMAX*9*128];
// pre-converted, pre-swizzled weights: 7 mats x (hi 32KB + lo 32KB)
// mat: 0=Wl[1],1=Wl[2],2=Wr[1],3=Wr[2],4=Wf[0],5=Wf[1],6=Wf[2]
__device__ __align__(16) char g_wb[7*65536];

// ---------------- helpers ----------------
__device__ __forceinline__ uint32_t smem_u32(const void*p){
    uint32_t a; asm("{ .reg .u64 t; cvta.to.shared.u64 t, %1; cvt.u32.u64 %0, t; }":"=r"(a):"l"(p)); return a;
}
__device__ __forceinline__ uint32_t pack2(float a,float b){
    __nv_bfloat162 t=__floats2bfloat162_rn(a,b); return *reinterpret_cast<uint32_t*>(&t);
}
__device__ __forceinline__ float bf_hi(float v){ return __bfloat162float(__float2bfloat16(v)); }

__device__ __forceinline__ void cvt8(const float* f, uint4& H, uint4& L){
    float h0=bf_hi(f[0]),h1=bf_hi(f[1]),h2=bf_hi(f[2]),h3=bf_hi(f[3]);
    float h4=bf_hi(f[4]),h5=bf_hi(f[5]),h6=bf_hi(f[6]),h7=bf_hi(f[7]);
    H=make_uint4(pack2(f[0],f[1]),pack2(f[2],f[3]),pack2(f[4],f[5]),pack2(f[6],f[7]));
    L=make_uint4(pack2(f[0]-h0,f[1]-h1),pack2(f[2]-h2,f[3]-h3),
                 pack2(f[4]-h4,f[5]-h5),pack2(f[6]-h6,f[7]-h7));
}

#define LDSM4(a0,a1,a2,a3,addr) \
    asm volatile("ldmatrix.sync.aligned.m8n8.x4.shared.b16 {%0,%1,%2,%3}, [%4];" \
        : "=r"(a0),"=r"(a1),"=r"(a2),"=r"(a3) : "r"(addr))

#define MMA_BF16(d,a,b) \
    asm volatile("mma.sync.aligned.m16n8k16.row.col.f32.bf16.bf16.f32 " \
        "{%0,%1,%2,%3},{%4,%5,%6,%7},{%8,%9},{%0,%1,%2,%3};" \
        : "+f"((d)[0]),"+f"((d)[1]),"+f"((d)[2]),"+f"((d)[3]) \
        : "r"((a)[0]),"r"((a)[1]),"r"((a)[2]),"r"((a)[3]),"r"((b)[0]),"r"((b)[1]))

// swizzled row layout: row r = 256B (16 chunks of 16B); chunk j stored at j^(r&7)
__device__ __forceinline__ uint32_t swz_off(int r,int ch){
    return (uint32_t)(r*256 + ((ch ^ (r&7))*16));
}

// 3-term split GEMM, CTA 64(M) x 128(N), K=128.
// 4 warps = 2(M) x 2(N); warp tile 32 x 64.
// Per kc per warp: 12 LDSM.x4 -> 48 MMAs  (1.0 smem-wavefront per MMA).
__device__ __forceinline__ void gemm64x128(
    uint32_t aH, uint32_t aL, uint32_t bH, uint32_t bL,
    int wM, int wN, int lane, float acc[2][8][4])
{
    const int rA = lane & 15, cA = lane >> 4;
    const int rB = (lane & 7) | ((lane >> 4) << 3);
    const int cB = (lane >> 3) & 1;
    const uint32_t aRow = (uint32_t)(wM*32 + rA) * 256;
    uint32_t bRow[4];
#pragma unroll
    for (int j = 0; j < 4; ++j) bRow[j] = (uint32_t)(wN*64 + j*16 + rB) * 256;
    const int sA = rA & 7, sB = rB & 7;
#pragma unroll
    for (int kc = 0; kc < 8; ++kc) {
        const uint32_t aoff = (uint32_t)(((kc*2 + cA) ^ sA) * 16);
        const uint32_t boff = (uint32_t)(((kc*2 + cB) ^ sB) * 16);
        uint32_t ah0[4],ah1[4],al0[4],al1[4];
        uint32_t bh[4][4], bl[4][4];
        LDSM4(ah0[0],ah0[1],ah0[2],ah0[3], aH + aRow + aoff);
        LDSM4(ah1[0],ah1[1],ah1[2],ah1[3], aH + aRow + 4096 + aoff);
        LDSM4(al0[0],al0[1],al0[2],al0[3], aL + aRow + aoff);
        LDSM4(al1[0],al1[1],al1[2],al1[3], aL + aRow + 4096 + aoff);
#pragma unroll
        for (int j = 0; j < 4; ++j) {
            LDSM4(bh[j][0],bh[j][1],bh[j][2],bh[j][3], bH + bRow[j] + boff);
            LDSM4(bl[j][0],bl[j][1],bl[j][2],bl[j][3], bL + bRow[j] + boff);
        }
        // pass (Ah, Bh)
#pragma unroll
        for (int j = 0; j < 4; ++j) {
            MMA_BF16(acc[0][2*j],   ah0, (&bh[j][0]));
            MMA_BF16(acc[0][2*j+1], ah0, (&bh[j][2]));
            MMA_BF16(acc[1][2*j],   ah1, (&bh[j][0]));
            MMA_BF16(acc[1][2*j+1], ah1, (&bh[j][2]));
        }
        // pass (Al, Bh)
#pragma unroll
        for (int j = 0; j < 4; ++j) {
            MMA_BF16(acc[0][2*j],   al0, (&bh[j][0]));
            MMA_BF16(acc[0][2*j+1], al0, (&bh[j][2]));
            MMA_BF16(acc[1][2*j],   al1, (&bh[j][0]));
            MMA_BF16(acc[1][2*j+1], al1, (&bh[j][2]));
        }
        // pass (Ah, Bl)
#pragma unroll
        for (int j = 0; j < 4; ++j) {
            MMA_BF16(acc[0][2*j],   ah0, (&bl[j][0]));
            MMA_BF16(acc[0][2*j+1], ah0, (&bl[j][2]));
            MMA_BF16(acc[1][2*j],   ah1, (&bl[j][0]));
            MMA_BF16(acc[1][2*j+1], ah1, (&bl[j][2]));
        }
    }
}

// ---------------- k0: pre-convert W -> bf16 hi/lo, pre-swizzled ----------
__global__ void __launch_bounds__(256)
k0_convw(const float* __restrict__ Wl,const float* __restrict__ Wr,
         const float* __restrict__ Wf){
    const int mat=blockIdx.x;   // 0..6
    const float* src;
    switch(mat){
        case 0: src=Wl+16384; break;
        case 1: src=Wl+32768; break;
        case 2: src=Wr+16384; break;
        case 3: src=Wr+32768; break;
        default: src=Wf+(mat-4)*16384; break;
    }
    char* dst=g_wb+(size_t)mat*65536;
    for(int i=threadIdx.x;i<2048;i+=256){
        int r=i>>4, ch=i&15;
        const float* p=src+r*128+ch*8;
        float f[8];
        float4 v0=*(const float4*)p, v1=*(const float4*)(p+4);
        f[0]=v0.x;f[1]=v0.y;f[2]=v0.z;f[3]=v0.w;f[4]=v1.x;f[5]=v1.y;f[6]=v1.z;f[7]=v1.w;
        uint4 H,L; cvt8(f,H,L);
        uint32_t o=swz_off(r,ch);
        *(uint4*)(dst+o)=H;
        *(uint4*)(dst+32768+o)=L;
    }
}

#define TTILE 4   // M-tiles per CTA

// ---------------- k1: xl/xr = x·W^T for l=1,2 (one side, TTILE tiles/CTA) --
#define K1_SMEM (3*32768)
__global__ void __launch_bounds__(128,2)
k1_linlr(const float* __restrict__ x,int N,int g1,int g2){
    int b=blockIdx.x;
    const int side = b >= (g1+g2);
    if(side) b -= (g1+g2);
    int l,den,npt;
    int tile0;
    if(b<g1){l=1;den=3;npt=21;tile0=b*TTILE;} else {l=2;den=5;npt=12;tile0=(b-g1)*TTILE;}
    const int Rl=den*npt;         // 63 or 60
    const int ll=l*l;
    const int ntiles=( (N+npt-1)/npt );

    extern __shared__ __align__(16) char sm[];
    const int AH=0, AL=16384, BH=32768;
    const uint32_t smb=smem_u32(sm);
    const int tid=threadIdx.x, lane=tid&31, warp=tid>>5;
    const int wM=warp>>1, wN=warp&1;

    // stage B once: pre-converted, pre-swizzled — straight 16B copy (64KB)
    {
        const char* wsrc=g_wb+(size_t)((side?2:0)+(l-1))*65536;
        for(int i=tid;i<4096;i+=128)
            *(uint4*)(sm+BH+i*16)=*(const uint4*)(wsrc+i*16);
    }
    float* gdst = side? g_xr : g_xl;

    for(int t=0;t<TTILE;++t){
        const int tile=tile0+t;
        if(tile>=ntiles) break;
        const int n0=tile*npt;

        // stage A: x rows -> bf16 hi/lo, swizzled (64 rows)
        for(int i=tid;i<1024;i+=128){
            int r=i>>4, ch=i&15;
            float f[8]={0,0,0,0,0,0,0,0};
            int nl=r/den, mi=r-nl*den, n=n0+nl;
            if(r<Rl && n<N){
                const float* p=x+((size_t)(n*9)+ll+mi)*128+ch*8;
                float4 v0=*(const float4*)p, v1=*(const float4*)(p+4);
                f[0]=v0.x;f[1]=v0.y;f[2]=v0.z;f[3]=v0.w;f[4]=v1.x;f[5]=v1.y;f[6]=v1.z;f[7]=v1.w;
            }
            uint4 H,L; cvt8(f,H,L);
            uint32_t o=swz_off(r,ch);
            *(uint4*)(sm+AH+o)=H; *(uint4*)(sm+AL+o)=L;
        }
        __syncthreads();

        float acc[2][8][4];
#pragma unroll
        for(int a0=0;a0<2;++a0)
#pragma unroll
            for(int a1=0;a1<8;++a1)
#pragma unroll
                for(int a2=0;a2<4;++a2) acc[a0][a1][a2]=0.f;

        gemm64x128(smb+AH, smb+AL, smb+BH, smb+BH+32768, wM, wN, lane, acc);

#pragma unroll
        for(int mt=0;mt<2;++mt){
#pragma unroll
            for(int h=0;h<2;++h){
                int r=wM*32+mt*16+(lane>>2)+h*8;
                if(r<Rl){
                    int nl=r/den, mi=r-nl*den, n=n0+nl;
                    if(n<N){
                        float* dst=gdst+((size_t)(n*8)+(ll-1)+mi)*128;
#pragma unroll
                        for(int nt=0;nt<8;++nt){
                            int c=wN*64+nt*8+(lane&3)*2;
                            *(float2*)(dst+c)=make_float2(acc[mt][nt][h*2],acc[mt][nt][h*2+1]);
                        }
                    }
                }
            }
        }
        __syncthreads();   // A buffer reuse barrier
    }
}

// ---------------- k2: tensor product -> tp (bf16 hi/lo) ----------------
__global__ void __launch_bounds__(256)
k2_tp(int N,TPCoef tpc){
    int t=blockIdx.x*256+threadIdx.x, n=t>>5, cq=t&31;
    if(n>=N)return;
    const float* pl=g_xl+(size_t)n*1024+cq*4;
    const float* pr=g_xr+(size_t)n*1024+cq*4;
    float xlv[8][4],xrv[8][4];
#pragma unroll
    for(int m=0;m<8;++m){
        float4 a=*(const float4*)(pl+m*128),b=*(const float4*)(pr+m*128);
        xlv[m][0]=a.x;xlv[m][1]=a.y;xlv[m][2]=a.z;xlv[m][3]=a.w;
        xrv[m][0]=b.x;xrv[m][1]=b.y;xrv[m][2]=b.z;xrv[m][3]=b.w;
    }
    float tp[9][4];
#pragma unroll
    for(int k=0;k<9;++k)
#pragma unroll
        for(int c=0;c<4;++c)tp[k][c]=0.f;
#pragma unroll
    for(int i=0;i<5;++i)
#pragma unroll
        for(int j=0;j<5;++j){ float cc=tpc.c220[i*5+j];
#pragma unroll
            for(int c=0;c<4;++c)tp[0][c]+=cc*xlv[3+i][c]*xrv[3+j][c]; }
#pragma unroll
    for(int i=0;i<3;++i)
#pragma unroll
        for(int j=0;j<5;++j)
#pragma unroll
            for(int k=0;k<3;++k){ float cc=tpc.c121[(i*5+j)*3+k];
#pragma unroll
                for(int c=0;c<4;++c)tp[1+k][c]+=cc*xlv[i][c]*xrv[3+j][c]; }
#pragma unroll
    for(int i=0;i<3;++i)
#pragma unroll
        for(int j=0;j<3;++j)
#pragma unroll
            for(int k=0;k<5;++k){ float cc=tpc.c112[(i*3+j)*5+k];
#pragma unroll
                for(int c=0;c<4;++c)tp[4+k][c]+=cc*xlv[i][c]*xrv[j][c]; }
#pragma unroll
    for(int mo=0;mo<9;++mo){
        float h0=bf_hi(tp[mo][0]),h1=bf_hi(tp[mo][1]),h2=bf_hi(tp[mo][2]),h3=bf_hi(tp[mo][3]);
        size_t idx=(size_t)(n*9+mo)*128+cq*4;
        *(uint2*)(g_tph+idx)=make_uint2(pack2(tp[mo][0],tp[mo][1]),pack2(tp[mo][2],tp[mo][3]));
        *(uint2*)(g_tpl+idx)=make_uint2(pack2(tp[mo][0]-h0,tp[mo][1]-h1),pack2(tp[mo][2]-h2,tp[mo][3]-h3));
    }
}

// ---------------- k3: out = tp·Wf^T (+bias l=0), TTILE tiles/CTA ----------
#define K3_SMEM (3*32768)
__global__ void __launch_bounds__(128,2)
k3_final(const float* __restrict__ bfv,
         float* __restrict__ out,int N,int g0,int g1){
    const int b=blockIdx.x;
    int l,den,npt,tile0;
    if(b<g0){l=0;den=1;npt=64;tile0=b*TTILE;}
    else if(b<g0+g1){l=1;den=3;npt=21;tile0=(b-g0)*TTILE;}
    else {l=2;den=5;npt=12;tile0=(b-g0-g1)*TTILE;}
    const int Rl=den*npt;
    const int ll=l*l;
    const int ntiles=(N+npt-1)/npt;

    extern __shared__ __align__(16) char sm[];
    const int AH=0, AL=16384, BH=32768;
    const uint32_t smb=smem_u32(sm);
    const int tid=threadIdx.x, lane=tid&31, warp=tid>>5;
    const int wM=warp>>1, wN=warp&1;

    // stage B once: pre-converted Wf — straight copy
    {
        const char* wsrc=g_wb+(size_t)(4+l)*65536;
        for(int i=tid;i<4096;i+=128)
            *(uint4*)(sm+BH+i*16)=*(const uint4*)(wsrc+i*16);
    }

    for(int t=0;t<TTILE;++t){
        const int tile=tile0+t;
        if(tile>=ntiles) break;
        const int n0=tile*npt;

        // stage A: tp (already bf16 hi/lo) — swizzled copy (64 rows)
        for(int i=tid;i<2048;i+=128){
            int half=i>>10, q=i&1023, r=q>>4, ch=q&15;
            uint4 v=make_uint4(0,0,0,0);
            int nl=r/den, mi=r-nl*den, n=n0+nl;
            if(r<Rl && n<N)
                v=*(const uint4*)((half?g_tpl:g_tph)+((size_t)(n*9)+ll+mi)*128+ch*8);
            *(uint4*)(sm+(half?AL:AH)+swz_off(r,ch))=v;
        }
        __syncthreads();

        float acc[2][8][4];
#pragma unroll
        for(int a0=0;a0<2;++a0)
#pragma unroll
            for(int a1=0;a1<8;++a1)
#pragma unroll
                for(int a2=0;a2<4;++a2) acc[a0][a1][a2]=0.f;

        gemm64x128(smb+AH, smb+AL, smb+BH, smb+BH+32768, wM, wN, lane, acc);

#pragma unroll
        for(int mt=0;mt<2;++mt){
#pragma unroll
            for(int h=0;h<2;++h){
                int r=wM*32+mt*16+(lane>>2)+h*8;
                if(r<Rl){
                    int nl=r/den, mi=r-nl*den, n=n0+nl;
                    if(n<N){
                        float* dst=out+((size_t)(n*9)+ll+mi)*128;
#pragma unroll
                        for(int nt=0;nt<8;++nt){
                            int c=wN*64+nt*8+(lane&3)*2;
                            float2 v=make_float2(acc[mt][nt][h*2],acc[mt][nt][h*2+1]);
                            if(l==0){ v.x+=bfv[c]; v.y+=bfv[c+1]; }
                            *(float2*)(dst+c)=v;
                        }
                    }
                }
            }
        }
        __syncthreads();
    }
}

// ---------------- Launch ----------------
extern "C" void kernel_launch(void* const* d_in,const int* in_sizes,int n_in,
                              void* d_out,int out_size){
    const float* x =(const float*)d_in[0];
    const float* Wl=(const float*)d_in[1];
    const float* Wr=(const float*)d_in[3];
    const float* Wf=(const float*)d_in[5];
    const float* bf=(const float*)d_in[6];
    float* out=(float*)d_out;
    const int N=in_sizes[0]/(9*128);

    TPCoef tpc;
    wigner3j_scaled(2,2,0,1.0f,            tpc.c220);
    wigner3j_scaled(1,2,1,std::sqrt(3.0f), tpc.c121);
    wigner3j_scaled(1,1,2,std::sqrt(5.0f), tpc.c112);

    cudaFuncSetAttribute(k1_linlr, cudaFuncAttributeMaxDynamicSharedMemorySize, K1_SMEM);
    cudaFuncSetAttribute(k3_final, cudaFuncAttributeMaxDynamicSharedMemorySize, K3_SMEM);

    const int t1=(N+20)/21, t2=(N+11)/12, t0=(N+63)/64;
    const int g1=(t1+TTILE-1)/TTILE, g2=(t2+TTILE-1)/TTILE, g0=(t0+TTILE-1)/TTILE;

    k0_convw<<<7,256>>>(Wl,Wr,Wf);
    k1_linlr<<<2*(g1+g2),128,K1_SMEM>>>(x,N,g1,g2);
    k2_tp<<<(N*32+255)/256,256>>>(N,tpc);
    k3_final<<<g0+g1+g2,128,K3_SMEM>>>(bf,out,N,g0,g1);
}

// round 9
// speedup vs baseline: 1.2424x; 1.2424x over previous
#include <cuda_runtime.h>
#include <cuda_bf16.h>
#include <cmath>
#include <complex>
#include <cstring>
#include <cstdint>

// ---------------- Host Wigner-3j (mirror of reference) ----------------
typedef std::complex<double> cd;
static double s_fact(int n){double r=1.0;for(int i=2;i<=n;++i)r*=i;return r;}
static double su2_cg(int j1,int m1,int j2,int m2,int j3,int m3){
    if(m3!=m1+m2)return 0.0;
    int vmin=-j1+j2+m3; if(-j1+m1>vmin)vmin=-j1+m1; if(0>vmin)vmin=0;
    int vmax=j2+j3+m1; if(j3-j1+j2<vmax)vmax=j3-j1+j2; if(j3+m3<vmax)vmax=j3+m3;
    double pref=std::sqrt((2.0*j3+1.0)*s_fact(j3+j1-j2)*s_fact(j3-j1+j2)*s_fact(j1+j2-j3)/s_fact(j1+j2+j3+1)
        *s_fact(j3+m3)*s_fact(j3-m3)/(s_fact(j1-m1)*s_fact(j1+m1)*s_fact(j2-m2)*s_fact(j2+m2)));
    double s=0.0;
    for(int v=vmin;v<=vmax;++v){
        double sg=((v+j2+m2)&1)?-1.0:1.0;
        s+=sg/s_fact(v)*s_fact(j2+j3+m1-v)*s_fact(j1-m1+v)
          /(s_fact(j3-j1+j2-v)*s_fact(j3+m3-v)*s_fact(v+j1-j2-m3));
    }
    return pref*s;
}
static void qmat(int l,cd*Q){
    int n=2*l+1; for(int i=0;i<n*n;++i)Q[i]=cd(0,0);
    double is2=1.0/std::sqrt(2.0);
    for(int m=-l;m<0;++m){Q[(l+m)*n+(l-m)]=cd(is2,0);Q[(l+m)*n+(l+m)]=cd(0,-is2);}
    Q[l*n+l]=cd(1,0);
    for(int m=1;m<=l;++m){double sg=(m&1)?-1.0:1.0;Q[(l+m)*n+(l+m)]=cd(sg*is2,0);Q[(l+m)*n+(l-m)]=cd(0,sg*is2);}
    cd f(1,0),mi(0,-1); for(int t=0;t<l;++t)f*=mi;
    for(int i=0;i<n*n;++i)Q[i]*=f;
}
static void wigner3j_scaled(int l1,int l2,int l3,float alpha,float*out){
    int n1=2*l1+1,n2=2*l2+1,n3=2*l3+1;
    cd Csu2[125];
    for(int i=0;i<n1;++i)for(int k=0;k<n2;++k)for(int n=0;n<n3;++n)
        Csu2[(i*n2+k)*n3+n]=cd(su2_cg(l1,i-l1,l2,k-l2,l3,n-l3),0);
    cd Q1[25],Q2[25],Q3[25]; qmat(l1,Q1);qmat(l2,Q2);qmat(l3,Q3);
    double Cr[125],norm2=0.0;
    for(int j=0;j<n1;++j)for(int l=0;l<n2;++l)for(int m=0;m<n3;++m){
        cd acc(0,0);
        for(int i=0;i<n1;++i)for(int k=0;k<n2;++k)for(int n=0;n<n3;++n)
            acc+=Q1[i*n1+j]*Q2[k*n2+l]*std::conj(Q3[n*n3+m])*Csu2[(i*n2+k)*n3+n];
        Cr[(j*n2+l)*n3+m]=acc.real(); norm2+=acc.real()*acc.real();
    }
    double inv=(double)alpha/std::sqrt(norm2);
    for(int t=0;t<n1*n2*n3;++t)out[t]=(float)(Cr[t]*inv);
}
struct TPCoef{float c220[25];float c121[45];float c112[45];};

// ---------------- Scratch (static device globals) ----------------
#define NMAX 50048
__device__ float g_xl[(size_t)NMAX*8*128];
__device__ float g_xr[(size_t)NMAX*8*128];
__device__ __nv_bfloat16 g_tph[(size_t)NMAX*9*128];
__device__ __nv_bfloat16 g_tpl[(size_t)NMAX*9*128];
// pre-converted, pre-swizzled weights: 7 mats x (hi 32KB + lo 32KB)
// mat: 0=Wl[1],1=Wl[2],2=Wr[1],3=Wr[2],4=Wf[0],5=Wf[1],6=Wf[2]
__device__ __align__(16) char g_wb[7*65536];

// ---------------- helpers ----------------
__device__ __forceinline__ uint32_t smem_u32(const void*p){
    uint32_t a; asm("{ .reg .u64 t; cvta.to.shared.u64 t, %1; cvt.u32.u64 %0, t; }":"=r"(a):"l"(p)); return a;
}
__device__ __forceinline__ uint32_t pack2(float a,float b){
    __nv_bfloat162 t=__floats2bfloat162_rn(a,b); return *reinterpret_cast<uint32_t*>(&t);
}
__device__ __forceinline__ float bf_hi(float v){ return __bfloat162float(__float2bfloat16(v)); }

__device__ __forceinline__ void cvt8(const float* f, uint4& H, uint4& L){
    float h0=bf_hi(f[0]),h1=bf_hi(f[1]),h2=bf_hi(f[2]),h3=bf_hi(f[3]);
    float h4=bf_hi(f[4]),h5=bf_hi(f[5]),h6=bf_hi(f[6]),h7=bf_hi(f[7]);
    H=make_uint4(pack2(f[0],f[1]),pack2(f[2],f[3]),pack2(f[4],f[5]),pack2(f[6],f[7]));
    L=make_uint4(pack2(f[0]-h0,f[1]-h1),pack2(f[2]-h2,f[3]-h3),
                 pack2(f[4]-h4,f[5]-h5),pack2(f[6]-h6,f[7]-h7));
}

#define LDSM4(a0,a1,a2,a3,addr) \
    asm volatile("ldmatrix.sync.aligned.m8n8.x4.shared.b16 {%0,%1,%2,%3}, [%4];" \
        : "=r"(a0),"=r"(a1),"=r"(a2),"=r"(a3) : "r"(addr))

#define MMA_BF16(d,a,b) \
    asm volatile("mma.sync.aligned.m16n8k16.row.col.f32.bf16.bf16.f32 " \
        "{%0,%1,%2,%3},{%4,%5,%6,%7},{%8,%9},{%0,%1,%2,%3};" \
        : "+f"((d)[0]),"+f"((d)[1]),"+f"((d)[2]),"+f"((d)[3]) \
        : "r"((a)[0]),"r"((a)[1]),"r"((a)[2]),"r"((a)[3]),"r"((b)[0]),"r"((b)[1]))

// swizzled row layout: row r = 256B (16 chunks of 16B); chunk j stored at j^(r&7)
__device__ __forceinline__ uint32_t swz_off(int r,int ch){
    return (uint32_t)(r*256 + ((ch ^ (r&7))*16));
}

// 3-term split GEMM with fragment reuse: CTA 64(M) x 128(N), K=128,
// 8 warps = 2(M) x 4(N), warp tile 32x32.  (R7 proven config)
__device__ __forceinline__ void gemm64x128(
    uint32_t aH, uint32_t aL, uint32_t bH, uint32_t bL,
    int wM, int wN, int lane, float acc[2][4][4])
{
    const int rA = lane & 15, cA = lane >> 4;
    const int rB = (lane & 7) | ((lane >> 4) << 3);
    const int cB = (lane >> 3) & 1;
    const uint32_t aRow  = (uint32_t)(wM*32 + rA) * 256;
    const uint32_t bRow0 = (uint32_t)(wN*32 + rB) * 256;
    const uint32_t bRow1 = bRow0 + 16*256;
    const int sA = rA & 7, sB = rB & 7;
#pragma unroll
    for (int kc = 0; kc < 8; ++kc) {
        const uint32_t aoff = (uint32_t)(((kc*2 + cA) ^ sA) * 16);
        const uint32_t boff = (uint32_t)(((kc*2 + cB) ^ sB) * 16);
        uint32_t ah0[4],ah1[4],al0[4],al1[4],bh0[4],bh1[4],bl0[4],bl1[4];
        LDSM4(ah0[0],ah0[1],ah0[2],ah0[3], aH + aRow + aoff);
        LDSM4(ah1[0],ah1[1],ah1[2],ah1[3], aH + aRow + 4096 + aoff);
        LDSM4(bh0[0],bh0[1],bh0[2],bh0[3], bH + bRow0 + boff);
        LDSM4(bh1[0],bh1[1],bh1[2],bh1[3], bH + bRow1 + boff);
        LDSM4(al0[0],al0[1],al0[2],al0[3], aL + aRow + aoff);
        LDSM4(al1[0],al1[1],al1[2],al1[3], aL + aRow + 4096 + aoff);
        LDSM4(bl0[0],bl0[1],bl0[2],bl0[3], bL + bRow0 + boff);
        LDSM4(bl1[0],bl1[1],bl1[2],bl1[3], bL + bRow1 + boff);
        MMA_BF16(acc[0][0],ah0,(&bh0[0])); MMA_BF16(acc[0][1],ah0,(&bh0[2]));
        MMA_BF16(acc[0][2],ah0,(&bh1[0])); MMA_BF16(acc[0][3],ah0,(&bh1[2]));
        MMA_BF16(acc[1][0],ah1,(&bh0[0])); MMA_BF16(acc[1][1],ah1,(&bh0[2]));
        MMA_BF16(acc[1][2],ah1,(&bh1[0])); MMA_BF16(acc[1][3],ah1,(&bh1[2]));
        MMA_BF16(acc[0][0],al0,(&bh0[0])); MMA_BF16(acc[0][1],al0,(&bh0[2]));
        MMA_BF16(acc[0][2],al0,(&bh1[0])); MMA_BF16(acc[0][3],al0,(&bh1[2]));
        MMA_BF16(acc[1][0],al1,(&bh0[0])); MMA_BF16(acc[1][1],al1,(&bh0[2]));
        MMA_BF16(acc[1][2],al1,(&bh1[0])); MMA_BF16(acc[1][3],al1,(&bh1[2]));
        MMA_BF16(acc[0][0],ah0,(&bl0[0])); MMA_BF16(acc[0][1],ah0,(&bl0[2]));
        MMA_BF16(acc[0][2],ah0,(&bl1[0])); MMA_BF16(acc[0][3],ah0,(&bl1[2]));
        MMA_BF16(acc[1][0],ah1,(&bl0[0])); MMA_BF16(acc[1][1],ah1,(&bl0[2]));
        MMA_BF16(acc[1][2],ah1,(&bl1[0])); MMA_BF16(acc[1][3],ah1,(&bl1[2]));
    }
}

// ---------------- k0: pre-convert W -> bf16 hi/lo, pre-swizzled ----------
__global__ void __launch_bounds__(256)
k0_convw(const float* __restrict__ Wl,const float* __restrict__ Wr,
         const float* __restrict__ Wf){
    const int mat=blockIdx.x;   // 0..6
    const float* src;
    switch(mat){
        case 0: src=Wl+16384; break;
        case 1: src=Wl+32768; break;
        case 2: src=Wr+16384; break;
        case 3: src=Wr+32768; break;
        default: src=Wf+(mat-4)*16384; break;
    }
    char* dst=g_wb+(size_t)mat*65536;
    for(int i=threadIdx.x;i<2048;i+=256){
        int r=i>>4, ch=i&15;
        const float* p=src+r*128+ch*8;
        float f[8];
        float4 v0=*(const float4*)p, v1=*(const float4*)(p+4);
        f[0]=v0.x;f[1]=v0.y;f[2]=v0.z;f[3]=v0.w;f[4]=v1.x;f[5]=v1.y;f[6]=v1.z;f[7]=v1.w;
        uint4 H,L; cvt8(f,H,L);
        uint32_t o=swz_off(r,ch);
        *(uint4*)(dst+o)=H;
        *(uint4*)(dst+32768+o)=L;
    }
}

#define TTILE 4   // M-tiles per CTA

// ------- k1: xl/xr = x·W^T for l=1,2, over n-chunk [nbase, nbase+ncnt) ----
#define K1_SMEM (3*32768)
__global__ void __launch_bounds__(256,2)
k1_linlr(const float* __restrict__ x,int nbase,int ncnt,int g1,int g2){
    int b=blockIdx.x;
    const int side = b >= (g1+g2);
    if(side) b -= (g1+g2);
    int l,den,npt,tile0;
    if(b<g1){l=1;den=3;npt=21;tile0=b*TTILE;} else {l=2;den=5;npt=12;tile0=(b-g1)*TTILE;}
    const int Rl=den*npt;
    const int ll=l*l;
    const int ntiles=(ncnt+npt-1)/npt;
    const int nend=nbase+ncnt;

    extern __shared__ __align__(16) char sm[];
    const int AH=0, AL=16384, BH=32768;
    const uint32_t smb=smem_u32(sm);
    const int tid=threadIdx.x, lane=tid&31, warp=tid>>5;
    const int wM=warp>>2, wN=warp&3;

    {   // stage B once
        const char* wsrc=g_wb+(size_t)((side?2:0)+(l-1))*65536;
        for(int i=tid;i<4096;i+=256)
            *(uint4*)(sm+BH+i*16)=*(const uint4*)(wsrc+i*16);
    }
    float* gdst = side? g_xr : g_xl;

    for(int t=0;t<TTILE;++t){
        const int tile=tile0+t;
        if(tile>=ntiles) break;
        const int n0=nbase+tile*npt;

        for(int i=tid;i<1024;i+=256){
            int r=i>>4, ch=i&15;
            float f[8]={0,0,0,0,0,0,0,0};
            int nl=r/den, mi=r-nl*den, n=n0+nl;
            if(r<Rl && n<nend){
                const float* p=x+((size_t)(n*9)+ll+mi)*128+ch*8;
                float4 v0=*(const float4*)p, v1=*(const float4*)(p+4);
                f[0]=v0.x;f[1]=v0.y;f[2]=v0.z;f[3]=v0.w;f[4]=v1.x;f[5]=v1.y;f[6]=v1.z;f[7]=v1.w;
            }
            uint4 H,L; cvt8(f,H,L);
            uint32_t o=swz_off(r,ch);
            *(uint4*)(sm+AH+o)=H; *(uint4*)(sm+AL+o)=L;
        }
        __syncthreads();

        float acc[2][4][4];
#pragma unroll
        for(int a0=0;a0<2;++a0)
#pragma unroll
            for(int a1=0;a1<4;++a1)
#pragma unroll
                for(int a2=0;a2<4;++a2) acc[a0][a1][a2]=0.f;

        gemm64x128(smb+AH, smb+AL, smb+BH, smb+BH+32768, wM, wN, lane, acc);

#pragma unroll
        for(int mt=0;mt<2;++mt){
#pragma unroll
            for(int h=0;h<2;++h){
                int r=wM*32+mt*16+(lane>>2)+h*8;
                if(r<Rl){
                    int nl=r/den, mi=r-nl*den, n=n0+nl;
                    if(n<nend){
                        float* dst=gdst+((size_t)(n*8)+(ll-1)+mi)*128;
#pragma unroll
                        for(int nt=0;nt<4;++nt){
                            int c=wN*32+nt*8+(lane&3)*2;
                            *(float2*)(dst+c)=make_float2(acc[mt][nt][h*2],acc[mt][nt][h*2+1]);
                        }
                    }
                }
            }
        }
        __syncthreads();
    }
}

// ---------------- k2: tensor product over n-chunk ----------------
__global__ void __launch_bounds__(256)
k2_tp(int nbase,int ncnt,TPCoef tpc){
    int t=blockIdx.x*256+threadIdx.x, nloc=t>>5, cq=t&31;
    if(nloc>=ncnt)return;
    int n=nbase+nloc;
    const float* pl=g_xl+(size_t)n*1024+cq*4;
    const float* pr=g_xr+(size_t)n*1024+cq*4;
    float xlv[8][4],xrv[8][4];
#pragma unroll
    for(int m=0;m<8;++m){
        float4 a=*(const float4*)(pl+m*128),b=*(const float4*)(pr+m*128);
        xlv[m][0]=a.x;xlv[m][1]=a.y;xlv[m][2]=a.z;xlv[m][3]=a.w;
        xrv[m][0]=b.x;xrv[m][1]=b.y;xrv[m][2]=b.z;xrv[m][3]=b.w;
    }
    float tp[9][4];
#pragma unroll
    for(int k=0;k<9;++k)
#pragma unroll
        for(int c=0;c<4;++c)tp[k][c]=0.f;
#pragma unroll
    for(int i=0;i<5;++i)
#pragma unroll
        for(int j=0;j<5;++j){ float cc=tpc.c220[i*5+j];
#pragma unroll
            for(int c=0;c<4;++c)tp[0][c]+=cc*xlv[3+i][c]*xrv[3+j][c]; }
#pragma unroll
    for(int i=0;i<3;++i)
#pragma unroll
        for(int j=0;j<5;++j)
#pragma unroll
            for(int k=0;k<3;++k){ float cc=tpc.c121[(i*5+j)*3+k];
#pragma unroll
                for(int c=0;c<4;++c)tp[1+k][c]+=cc*xlv[i][c]*xrv[3+j][c]; }
#pragma unroll
    for(int i=0;i<3;++i)
#pragma unroll
        for(int j=0;j<3;++j)
#pragma unroll
            for(int k=0;k<5;++k){ float cc=tpc.c112[(i*3+j)*5+k];
#pragma unroll
                for(int c=0;c<4;++c)tp[4+k][c]+=cc*xlv[i][c]*xrv[j][c]; }
#pragma unroll
    for(int mo=0;mo<9;++mo){
        float h0=bf_hi(tp[mo][0]),h1=bf_hi(tp[mo][1]),h2=bf_hi(tp[mo][2]),h3=bf_hi(tp[mo][3]);
        size_t idx=(size_t)(n*9+mo)*128+cq*4;
        *(uint2*)(g_tph+idx)=make_uint2(pack2(tp[mo][0],tp[mo][1]),pack2(tp[mo][2],tp[mo][3]));
        *(uint2*)(g_tpl+idx)=make_uint2(pack2(tp[mo][0]-h0,tp[mo][1]-h1),pack2(tp[mo][2]-h2,tp[mo][3]-h3));
    }
}

// ------- k3: out = tp·Wf^T (+bias l=0), over n-chunk ----------
#define K3_SMEM (3*32768)
__global__ void __launch_bounds__(256,2)
k3_final(const float* __restrict__ bfv,
         float* __restrict__ out,int nbase,int ncnt,int g0,int g1){
    const int b=blockIdx.x;
    int l,den,npt,tile0;
    if(b<g0){l=0;den=1;npt=64;tile0=b*TTILE;}
    else if(b<g0+g1){l=1;den=3;npt=21;tile0=(b-g0)*TTILE;}
    else {l=2;den=5;npt=12;tile0=(b-g0-g1)*TTILE;}
    const int Rl=den*npt;
    const int ll=l*l;
    const int ntiles=(ncnt+npt-1)/npt;
    const int nend=nbase+ncnt;

    extern __shared__ __align__(16) char sm[];
    const int AH=0, AL=16384, BH=32768;
    const uint32_t smb=smem_u32(sm);
    const int tid=threadIdx.x, lane=tid&31, warp=tid>>5;
    const int wM=warp>>2, wN=warp&3;

    {   // stage B once
        const char* wsrc=g_wb+(size_t)(4+l)*65536;
        for(int i=tid;i<4096;i+=256)
            *(uint4*)(sm+BH+i*16)=*(const uint4*)(wsrc+i*16);
    }

    for(int t=0;t<TTILE;++t){
        const int tile=tile0+t;
        if(tile>=ntiles) break;
        const int n0=nbase+tile*npt;

        for(int i=tid;i<2048;i+=256){
            int half=i>>10, q=i&1023, r=q>>4, ch=q&15;
            uint4 v=make_uint4(0,0,0,0);
            int nl=r/den, mi=r-nl*den, n=n0+nl;
            if(r<Rl && n<nend)
                v=*(const uint4*)((half?g_tpl:g_tph)+((size_t)(n*9)+ll+mi)*128+ch*8);
            *(uint4*)(sm+(half?AL:AH)+swz_off(r,ch))=v;
        }
        __syncthreads();

        float acc[2][4][4];
#pragma unroll
        for(int a0=0;a0<2;++a0)
#pragma unroll
            for(int a1=0;a1<4;++a1)
#pragma unroll
                for(int a2=0;a2<4;++a2) acc[a0][a1][a2]=0.f;

        gemm64x128(smb+AH, smb+AL, smb+BH, smb+BH+32768, wM, wN, lane, acc);

#pragma unroll
        for(int mt=0;mt<2;++mt){
#pragma unroll
            for(int h=0;h<2;++h){
                int r=wM*32+mt*16+(lane>>2)+h*8;
                if(r<Rl){
                    int nl=r/den, mi=r-nl*den, n=n0+nl;
                    if(n<nend){
                        float* dst=out+((size_t)(n*9)+ll+mi)*128;
#pragma unroll
                        for(int nt=0;nt<4;++nt){
                            int c=wN*32+nt*8+(lane&3)*2;
                            float2 v=make_float2(acc[mt][nt][h*2],acc[mt][nt][h*2+1]);
                            if(l==0){ v.x+=bfv[c]; v.y+=bfv[c+1]; }
                            *(float2*)(dst+c)=v;
                        }
                    }
                }
            }
        }
        __syncthreads();
    }
}

// ---------------- Launch: 2 chunks on 2 forked streams ----------------
extern "C" void kernel_launch(void* const* d_in,const int* in_sizes,int n_in,
                              void* d_out,int out_size){
    const float* x =(const float*)d_in[0];
    const float* Wl=(const float*)d_in[1];
    const float* Wr=(const float*)d_in[3];
    const float* Wf=(const float*)d_in[5];
    const float* bf=(const float*)d_in[6];
    float* out=(float*)d_out;
    const int N=in_sizes[0]/(9*128);

    TPCoef tpc;
    wigner3j_scaled(2,2,0,1.0f,            tpc.c220);
    wigner3j_scaled(1,2,1,std::sqrt(3.0f), tpc.c121);
    wigner3j_scaled(1,1,2,std::sqrt(5.0f), tpc.c112);

    static bool init=false;
    static cudaStream_t s1,s2;
    static cudaEvent_t evFork,evJ1,evJ2;
    if(!init){
        cudaStreamCreateWithFlags(&s1,cudaStreamNonBlocking);
        cudaStreamCreateWithFlags(&s2,cudaStreamNonBlocking);
        cudaEventCreateWithFlags(&evFork,cudaEventDisableTiming);
        cudaEventCreateWithFlags(&evJ1,cudaEventDisableTiming);
        cudaEventCreateWithFlags(&evJ2,cudaEventDisableTiming);
        cudaFuncSetAttribute(k1_linlr, cudaFuncAttributeMaxDynamicSharedMemorySize, K1_SMEM);
        cudaFuncSetAttribute(k3_final, cudaFuncAttributeMaxDynamicSharedMemorySize, K3_SMEM);
        init=true;
    }

    // k0 on the (captured) legacy stream, then fork into 2 n-chunks
    k0_convw<<<7,256>>>(Wl,Wr,Wf);
    cudaEventRecord(evFork,0);
    cudaStreamWaitEvent(s1,evFork,0);
    cudaStreamWaitEvent(s2,evFork,0);

    const int nb[3]={0, N/2, N};
    cudaStream_t ss[2]={s1,s2};
    for(int c=0;c<2;++c){
        int nbase=nb[c], ncnt=nb[c+1]-nb[c];
        cudaStream_t s=ss[c];
        const int t1=(ncnt+20)/21, t2=(ncnt+11)/12, t0=(ncnt+63)/64;
        const int g1=(t1+TTILE-1)/TTILE, g2=(t2+TTILE-1)/TTILE, g0=(t0+TTILE-1)/TTILE;
        k1_linlr<<<2*(g1+g2),256,K1_SMEM,s>>>(x,nbase,ncnt,g1,g2);
        k2_tp<<<(ncnt*32+255)/256,256,0,s>>>(nbase,ncnt,tpc);
        k3_final<<<g0+g1+g2,256,K3_SMEM,s>>>(bf,out,nbase,ncnt,g0,g1);
    }

    cudaEventRecord(evJ1,s1);
    cudaEventRecord(evJ2,s2);
    cudaStreamWaitEvent(0,evJ1,0);
    cudaStreamWaitEvent(0,evJ2,0);
}